// round 9
// baseline (speedup 1.0000x reference)
#include <cuda_runtime.h>

#define NN 2048
#define OUTC 16
#define SBLK 128            // stats blocks (16 rows each)

// ---- scratch (device globals; every word overwritten each call, no atomics) ----
__device__ float g_rowsum[NN];
__device__ float g_diag[NN];
__device__ float g_cpart[SBLK * NN];  // per-block colsum partials (1 MB)
__device__ float g_Rf[NN * OUTC];     // per-i vector (incl. trace/totsum terms)
__device__ float g_Cc[NN * OUTC];     // per-j vector
__device__ float g_Dd[NN * OUTC];     // diagonal extras

// ---------------------------------------------------------------------------
// Single pass over A: rowsum + diag (direct) + colsum partials (per block).
// 128 blocks x 256 thr; block owns rows 16b..16b+15; thread owns fixed cols.
__global__ __launch_bounds__(256) void k_stats(const float* __restrict__ A) {
    __shared__ float sred[16][8];
    int t = threadIdx.x, lane = t & 31, w = t >> 5;
    int r0 = blockIdx.x * 16;

    float4 ca0 = make_float4(0.f, 0.f, 0.f, 0.f);
    float4 ca1 = make_float4(0.f, 0.f, 0.f, 0.f);

    #pragma unroll
    for (int r = 0; r < 16; r++) {
        const float4* row = (const float4*)(A + (size_t)(r0 + r) * NN);
        float4 v0 = row[t];          // cols 4t..4t+3
        float4 v1 = row[t + 256];    // cols 1024+4t..
        ca0.x += v0.x; ca0.y += v0.y; ca0.z += v0.z; ca0.w += v0.w;
        ca1.x += v1.x; ca1.y += v1.y; ca1.z += v1.z; ca1.w += v1.w;
        float rs = (v0.x + v0.y) + (v0.z + v0.w) + (v1.x + v1.y) + (v1.z + v1.w);
        #pragma unroll
        for (int off = 16; off; off >>= 1) rs += __shfl_xor_sync(0xffffffffu, rs, off);
        if (lane == 0) sred[r][w] = rs;
    }

    // colsum partials: coalesced float4 stores, block-exclusive row of g_cpart
    *(float4*)(g_cpart + (size_t)blockIdx.x * NN + 4 * t)        = ca0;
    *(float4*)(g_cpart + (size_t)blockIdx.x * NN + 1024 + 4 * t) = ca1;

    __syncthreads();
    if (t < 16) {
        float s = 0.f;
        #pragma unroll
        for (int q = 0; q < 8; q++) s += sred[t][q];
        g_rowsum[r0 + t] = s;
        g_diag[r0 + t]   = A[(size_t)(r0 + t) * NN + (r0 + t)];
    }
}

// ---------------------------------------------------------------------------
// k_pre: 32 blocks x 256. Block reduces colsum for its 64 columns from
// g_cpart, reduces trace/totsum, then writes Rf/Cc/Dd float4 chunks.
__global__ __launch_bounds__(256) void k_pre(const float* __restrict__ W) {
    __shared__ float scp[4][64];
    __shared__ float scol[64];
    __shared__ float sr8[8], ss8[8];
    __shared__ float s_sc[2];
    int t = threadIdx.x, lane = t & 31, w = t >> 5;
    int j0 = blockIdx.x * 64;

    // ---- colsum for this block's 64 columns (4 partial groups) ----
    {
        int cl = t & 63, cg = t >> 6;
        float s0 = 0.f, s1 = 0.f;
        for (int p = cg; p < SBLK; p += 8) {          // 2 indep streams
            s0 += g_cpart[(size_t)p * NN + j0 + cl];
            s1 += g_cpart[(size_t)(p + 4) * NN + j0 + cl];
        }
        scp[cg & 3][cl] = 0.f;                         // init via first write trick below
        __syncthreads();
        // 8 groups -> fold into 4 via atomic-free two-step: use (cg&3) slot sum
        // simpler: each of 8 groups adds into scp with two-phase
        // phase 1: groups 0..3 write, phase 2: groups 4..7 add
        if (cg < 4) scp[cg][cl] = s0 + s1;
        __syncthreads();
        if (cg >= 4) scp[cg - 4][cl] += s0 + s1;
        __syncthreads();
        if (t < 64) scol[t] = scp[0][t] + scp[1][t] + scp[2][t] + scp[3][t];
    }

    // ---- trace / totsum ----
    float tr = 0.f, ts = 0.f;
    #pragma unroll
    for (int q = 0; q < 8; q++) {
        tr += g_diag[t + 256 * q];
        ts += g_rowsum[t + 256 * q];
    }
    #pragma unroll
    for (int off = 16; off; off >>= 1) {
        tr += __shfl_xor_sync(0xffffffffu, tr, off);
        ts += __shfl_xor_sync(0xffffffffu, ts, off);
    }
    if (lane == 0) { sr8[w] = tr; ss8[w] = ts; }
    __syncthreads();
    if (t == 0) {
        float a = 0.f, b = 0.f;
        #pragma unroll
        for (int q = 0; q < 8; q++) { a += sr8[q]; b += ss8[q]; }
        s_sc[0] = a; s_sc[1] = b;
    }
    __syncthreads();
    float trv = s_sc[0], tsv = s_sc[1];

    // ---- per-i vectors: thread -> (i, float4 chunk) ----
    int il = t >> 2, c4 = t & 3;
    int i = j0 + il;
    float di = g_diag[i], ri = g_rowsum[i], ci = scol[il];

    float4 w0  = *(const float4*)(W + 0*16  + c4*4);
    float4 w1  = *(const float4*)(W + 1*16  + c4*4);
    float4 w2  = *(const float4*)(W + 2*16  + c4*4);
    float4 w3  = *(const float4*)(W + 3*16  + c4*4);
    float4 w4  = *(const float4*)(W + 4*16  + c4*4);
    float4 w5  = *(const float4*)(W + 5*16  + c4*4);
    float4 w6  = *(const float4*)(W + 6*16  + c4*4);
    float4 w7  = *(const float4*)(W + 7*16  + c4*4);
    float4 w8  = *(const float4*)(W + 8*16  + c4*4);
    float4 w9  = *(const float4*)(W + 9*16  + c4*4);
    float4 w10 = *(const float4*)(W + 10*16 + c4*4);
    float4 w13 = *(const float4*)(W + 13*16 + c4*4);
    float4 w14 = *(const float4*)(W + 14*16 + c4*4);

    float4 rf, cc, dd;
    rf.x = fmaf(di,w8.x, fmaf(ri,w9.x, fmaf(ci,w10.x, fmaf(trv,w13.x, tsv*w14.x))));
    rf.y = fmaf(di,w8.y, fmaf(ri,w9.y, fmaf(ci,w10.y, fmaf(trv,w13.y, tsv*w14.y))));
    rf.z = fmaf(di,w8.z, fmaf(ri,w9.z, fmaf(ci,w10.z, fmaf(trv,w13.z, tsv*w14.z))));
    rf.w = fmaf(di,w8.w, fmaf(ri,w9.w, fmaf(ci,w10.w, fmaf(trv,w13.w, tsv*w14.w))));
    cc.x = fmaf(di,w5.x, fmaf(ri,w6.x, ci*w7.x));
    cc.y = fmaf(di,w5.y, fmaf(ri,w6.y, ci*w7.y));
    cc.z = fmaf(di,w5.z, fmaf(ri,w6.z, ci*w7.z));
    cc.w = fmaf(di,w5.w, fmaf(ri,w6.w, ci*w7.w));
    dd.x = fmaf(di,w0.x, fmaf(ri,w1.x, fmaf(ci,w2.x, fmaf(trv,w3.x, tsv*w4.x))));
    dd.y = fmaf(di,w0.y, fmaf(ri,w1.y, fmaf(ci,w2.y, fmaf(trv,w3.y, tsv*w4.y))));
    dd.z = fmaf(di,w0.z, fmaf(ri,w1.z, fmaf(ci,w2.z, fmaf(trv,w3.z, tsv*w4.z))));
    dd.w = fmaf(di,w0.w, fmaf(ri,w1.w, fmaf(ci,w2.w, fmaf(trv,w3.w, tsv*w4.w))));

    *(float4*)(g_Rf + i*OUTC + c4*4) = rf;
    *(float4*)(g_Cc + i*OUTC + c4*4) = cc;
    *(float4*)(g_Dd + i*OUTC + c4*4) = dd;
}

// ---------------------------------------------------------------------------
__device__ __forceinline__ float4 f4add(float4 a, float4 b) {
    return make_float4(a.x + b.x, a.y + b.y, a.z + b.z, a.w + b.w);
}
__device__ __forceinline__ float4 f4fma(float s, float4 w, float4 acc) {
    return make_float4(fmaf(s, w.x, acc.x), fmaf(s, w.y, acc.y),
                       fmaf(s, w.z, acc.z), fmaf(s, w.w, acc.w));
}

// 32x32 output tile per block. Lane layout: lane = jsub*4 + c4 so every
// STG.128 / Cc LDG.128 is a fully-contiguous 512B warp transaction.
__global__ __launch_bounds__(256, 4) void k_main(const float* __restrict__ A,
                                                 const float* __restrict__ W,
                                                 float* __restrict__ out) {
    __shared__ float sT[32][33];      // A[j][i] tile (transposed source)
    __shared__ float sA[32][33];      // A[i][j] tile
    __shared__ float4 sw11[4], sw12[4];
    int t = threadIdx.x;
    int j0 = blockIdx.x * 32, i0 = blockIdx.y * 32;

    if (t < 4)      sw11[t]     = *(const float4*)(W + 11*16 + t*4);
    else if (t < 8) sw12[t - 4] = *(const float4*)(W + 12*16 + (t-4)*4);

    #pragma unroll
    for (int k = 0; k < 4; k++) {
        int e = t + 256 * k;
        int r = e >> 5, c = e & 31;
        sT[r][c] = A[(size_t)(j0 + r) * NN + i0 + c];   // rows j0.., cols i0..
        sA[r][c] = A[(size_t)(i0 + r) * NN + j0 + c];   // rows i0.., cols j0..
    }
    __syncthreads();

    int wi = t >> 5, lane = t & 31;
    int jsub = lane >> 2, c4 = lane & 3;
    float4 w11c = sw11[c4], w12c = sw12[c4];

    // warp's i range: i0 + wi*4 .. +3 ; hoist Rf chunks (broadcast loads)
    float4 rf[4];
    #pragma unroll
    for (int k = 0; k < 4; k++)
        rf[k] = *(const float4*)(g_Rf + (size_t)(i0 + wi*4 + k) * OUTC + c4*4);

    #pragma unroll
    for (int jg = 0; jg < 4; jg++) {
        int jj = jg * 8 + jsub;
        int j  = j0 + jj;
        float4 cc = *(const float4*)(g_Cc + (size_t)j * OUTC + c4*4);  // coalesced

        #pragma unroll
        for (int k = 0; k < 4; k++) {
            int ii = wi * 4 + k;
            int i  = i0 + ii;
            float av = sA[ii][jj];
            float tv = sT[jj][ii];
            float4 o = f4fma(av, w12c, f4fma(tv, w11c, f4add(rf[k], cc)));
            if (i == j)
                o = f4add(o, *(const float4*)(g_Dd + (size_t)i * OUTC + c4*4));
            *(float4*)(out + ((size_t)i * NN + j) * OUTC + c4*4) = o;   // coalesced
        }
    }
}

extern "C" void kernel_launch(void* const* d_in, const int* in_sizes, int n_in,
                              void* d_out, int out_size) {
    const float* A = (const float*)d_in[0];
    const float* W = (const float*)d_in[1];
    float* out = (float*)d_out;

    k_stats<<<SBLK, 256>>>(A);
    k_pre<<<32, 256>>>(W);
    k_main<<<dim3(64, 64), 256>>>(A, W, out);
}

// round 11
// speedup vs baseline: 1.0450x; 1.0450x over previous
#include <cuda_runtime.h>

#define NN 2048
#define OUTC 16
#define SBLK 256            // stats blocks (8 rows each)

// ---- scratch (device globals; every word overwritten each call, no atomics) ----
__device__ float g_rowsum[NN];
__device__ float g_diag[NN];
__device__ float g_cpart[SBLK * NN];  // per-block colsum partials (2 MB)
__device__ float g_Rf[NN * OUTC];     // per-i vector (incl. trace/totsum terms)
__device__ float g_Cc[NN * OUTC];     // per-j vector
__device__ float g_Dd[NN * OUTC];     // diagonal extras

// ---------------------------------------------------------------------------
// Single pass over A: rowsum + diag (direct) + colsum partials (per block).
// 256 blocks x 512 thr; block owns 8 rows; thread owns 4 fixed cols. MLP=8.
__global__ __launch_bounds__(512) void k_stats(const float* __restrict__ A) {
    __shared__ float sred[8][16];
    int t = threadIdx.x, lane = t & 31, w = t >> 5;   // 16 warps
    int r0 = blockIdx.x * 8;

    float4 ca = make_float4(0.f, 0.f, 0.f, 0.f);

    #pragma unroll
    for (int r = 0; r < 8; r++) {
        float4 v = ((const float4*)(A + (size_t)(r0 + r) * NN))[t];   // cols 4t..4t+3
        ca.x += v.x; ca.y += v.y; ca.z += v.z; ca.w += v.w;
        float rs = (v.x + v.y) + (v.z + v.w);
        #pragma unroll
        for (int off = 16; off; off >>= 1) rs += __shfl_xor_sync(0xffffffffu, rs, off);
        if (lane == 0) sred[r][w] = rs;
    }

    // colsum partials: coalesced float4 store, block-exclusive row of g_cpart
    *(float4*)(g_cpart + (size_t)blockIdx.x * NN + 4 * t) = ca;

    __syncthreads();
    if (t < 8) {
        float s = 0.f;
        #pragma unroll
        for (int q = 0; q < 16; q++) s += sred[t][q];
        g_rowsum[r0 + t] = s;
        g_diag[r0 + t]   = A[(size_t)(r0 + t) * NN + (r0 + t)];
    }
}

// ---------------------------------------------------------------------------
// k_pre: 32 blocks x 256. Block reduces colsum for its 64 columns from
// g_cpart (L2-resident), reduces trace/totsum, writes Rf/Cc/Dd float4 chunks.
__global__ __launch_bounds__(256) void k_pre(const float* __restrict__ W) {
    __shared__ float scp[4][64];
    __shared__ float scol[64];
    __shared__ float sr8[8], ss8[8];
    __shared__ float s_sc[2];
    int t = threadIdx.x, lane = t & 31, w = t >> 5;
    int j0 = blockIdx.x * 64;

    // ---- colsum for this block's 64 columns: 4 groups x 64 partials each ----
    {
        int cl = t & 63, cg = t >> 6;      // cg in 0..3
        int pbase = cg * 64;
        float acc = 0.f;
        #pragma unroll 8
        for (int p = pbase; p < pbase + 64; p++)
            acc += g_cpart[(size_t)p * NN + j0 + cl];
        scp[cg][cl] = acc;
        __syncthreads();
        if (t < 64) scol[t] = (scp[0][t] + scp[1][t]) + (scp[2][t] + scp[3][t]);
    }

    // ---- trace / totsum ----
    float tr = 0.f, ts = 0.f;
    #pragma unroll
    for (int q = 0; q < 8; q++) {
        tr += g_diag[t + 256 * q];
        ts += g_rowsum[t + 256 * q];
    }
    #pragma unroll
    for (int off = 16; off; off >>= 1) {
        tr += __shfl_xor_sync(0xffffffffu, tr, off);
        ts += __shfl_xor_sync(0xffffffffu, ts, off);
    }
    if (lane == 0) { sr8[w] = tr; ss8[w] = ts; }
    __syncthreads();
    if (t == 0) {
        float a = 0.f, b = 0.f;
        #pragma unroll
        for (int q = 0; q < 8; q++) { a += sr8[q]; b += ss8[q]; }
        s_sc[0] = a; s_sc[1] = b;
    }
    __syncthreads();
    float trv = s_sc[0], tsv = s_sc[1];

    // ---- per-i vectors: thread -> (i, float4 chunk) ----
    int il = t >> 2, c4 = t & 3;
    int i = j0 + il;
    float di = g_diag[i], ri = g_rowsum[i], ci = scol[il];

    float4 w0  = *(const float4*)(W + 0*16  + c4*4);
    float4 w1  = *(const float4*)(W + 1*16  + c4*4);
    float4 w2  = *(const float4*)(W + 2*16  + c4*4);
    float4 w3  = *(const float4*)(W + 3*16  + c4*4);
    float4 w4  = *(const float4*)(W + 4*16  + c4*4);
    float4 w5  = *(const float4*)(W + 5*16  + c4*4);
    float4 w6  = *(const float4*)(W + 6*16  + c4*4);
    float4 w7  = *(const float4*)(W + 7*16  + c4*4);
    float4 w8  = *(const float4*)(W + 8*16  + c4*4);
    float4 w9  = *(const float4*)(W + 9*16  + c4*4);
    float4 w10 = *(const float4*)(W + 10*16 + c4*4);
    float4 w13 = *(const float4*)(W + 13*16 + c4*4);
    float4 w14 = *(const float4*)(W + 14*16 + c4*4);

    float4 rf, cc, dd;
    rf.x = fmaf(di,w8.x, fmaf(ri,w9.x, fmaf(ci,w10.x, fmaf(trv,w13.x, tsv*w14.x))));
    rf.y = fmaf(di,w8.y, fmaf(ri,w9.y, fmaf(ci,w10.y, fmaf(trv,w13.y, tsv*w14.y))));
    rf.z = fmaf(di,w8.z, fmaf(ri,w9.z, fmaf(ci,w10.z, fmaf(trv,w13.z, tsv*w14.z))));
    rf.w = fmaf(di,w8.w, fmaf(ri,w9.w, fmaf(ci,w10.w, fmaf(trv,w13.w, tsv*w14.w))));
    cc.x = fmaf(di,w5.x, fmaf(ri,w6.x, ci*w7.x));
    cc.y = fmaf(di,w5.y, fmaf(ri,w6.y, ci*w7.y));
    cc.z = fmaf(di,w5.z, fmaf(ri,w6.z, ci*w7.z));
    cc.w = fmaf(di,w5.w, fmaf(ri,w6.w, ci*w7.w));
    dd.x = fmaf(di,w0.x, fmaf(ri,w1.x, fmaf(ci,w2.x, fmaf(trv,w3.x, tsv*w4.x))));
    dd.y = fmaf(di,w0.y, fmaf(ri,w1.y, fmaf(ci,w2.y, fmaf(trv,w3.y, tsv*w4.y))));
    dd.z = fmaf(di,w0.z, fmaf(ri,w1.z, fmaf(ci,w2.z, fmaf(trv,w3.z, tsv*w4.z))));
    dd.w = fmaf(di,w0.w, fmaf(ri,w1.w, fmaf(ci,w2.w, fmaf(trv,w3.w, tsv*w4.w))));

    *(float4*)(g_Rf + i*OUTC + c4*4) = rf;
    *(float4*)(g_Cc + i*OUTC + c4*4) = cc;
    *(float4*)(g_Dd + i*OUTC + c4*4) = dd;
}

// ---------------------------------------------------------------------------
__device__ __forceinline__ float4 f4add(float4 a, float4 b) {
    return make_float4(a.x + b.x, a.y + b.y, a.z + b.z, a.w + b.w);
}
__device__ __forceinline__ float4 f4fma(float s, float4 w, float4 acc) {
    return make_float4(fmaf(s, w.x, acc.x), fmaf(s, w.y, acc.y),
                       fmaf(s, w.z, acc.z), fmaf(s, w.w, acc.w));
}

// Paired-tile k_main: block (bx,by), by<=bx, computes output tiles
// (rows by-tile, cols bx-tile) AND (rows bx-tile, cols by-tile) from the
// same two smem tiles -> halves A read. Lane layout keeps all STG.128 /
// Cc LDG.128 fully contiguous 512B warp transactions.
__global__ __launch_bounds__(256, 4) void k_main(const float* __restrict__ A,
                                                 const float* __restrict__ W,
                                                 float* __restrict__ out) {
    int bx = blockIdx.x, by = blockIdx.y;
    if (by > bx) return;

    __shared__ float sP[32][33];      // A[rows by-tile][cols bx-tile]
    __shared__ float sQ[32][33];      // A[rows bx-tile][cols by-tile]
    __shared__ float4 sw11[4], sw12[4];
    int t = threadIdx.x;
    int a0 = by * 32, b0 = bx * 32;   // a0 = lower base, b0 = upper base

    if (t < 4)      sw11[t]     = *(const float4*)(W + 11*16 + t*4);
    else if (t < 8) sw12[t - 4] = *(const float4*)(W + 12*16 + (t-4)*4);

    #pragma unroll
    for (int k = 0; k < 4; k++) {
        int e = t + 256 * k;
        int r = e >> 5, c = e & 31;
        sP[r][c] = A[(size_t)(a0 + r) * NN + b0 + c];
        if (bx != by)
            sQ[r][c] = A[(size_t)(b0 + r) * NN + a0 + c];
    }
    __syncthreads();

    int wi = t >> 5, lane = t & 31;
    int jsub = lane >> 2, c4 = lane & 3;
    float4 w11c = sw11[c4], w12c = sw12[c4];
    int npass = (bx == by) ? 1 : 2;

    for (int pass = 0; pass < npass; pass++) {
        // pass 0: rows a0.., cols b0..  (av from sP, tv from sQ)
        // pass 1: rows b0.., cols a0..  (av from sQ, tv from sP)
        int i0 = pass ? b0 : a0;
        int j0 = pass ? a0 : b0;
        float (*sav)[33] = pass ? sQ : sP;
        float (*stv)[33] = pass ? sP : sQ;
        if (bx == by) { sav = sP; stv = sP; }   // diagonal block: single tile

        float4 rf[4];
        #pragma unroll
        for (int k = 0; k < 4; k++)
            rf[k] = *(const float4*)(g_Rf + (size_t)(i0 + wi*4 + k) * OUTC + c4*4);

        #pragma unroll
        for (int jg = 0; jg < 4; jg++) {
            int jj = jg * 8 + jsub;
            int j  = j0 + jj;
            float4 cc = *(const float4*)(g_Cc + (size_t)j * OUTC + c4*4);

            #pragma unroll
            for (int k = 0; k < 4; k++) {
                int ii = wi * 4 + k;
                int i  = i0 + ii;
                float av = sav[ii][jj];
                float tv = stv[jj][ii];
                float4 o = f4fma(av, w12c, f4fma(tv, w11c, f4add(rf[k], cc)));
                if (i == j)
                    o = f4add(o, *(const float4*)(g_Dd + (size_t)i * OUTC + c4*4));
                *(float4*)(out + ((size_t)i * NN + j) * OUTC + c4*4) = o;
            }
        }
    }
}

extern "C" void kernel_launch(void* const* d_in, const int* in_sizes, int n_in,
                              void* d_out, int out_size) {
    const float* A = (const float*)d_in[0];
    const float* W = (const float*)d_in[1];
    float* out = (float*)d_out;

    k_stats<<<SBLK, 512>>>(A);
    k_pre<<<32, 256>>>(W);
    k_main<<<dim3(64, 64), 256>>>(A, W, out);
}

// round 14
// speedup vs baseline: 1.0736x; 1.0274x over previous
#include <cuda_runtime.h>

#define NN 2048
#define OUTC 16
#define SBLK 256            // stats blocks (8 rows each)

// ---- scratch (device globals; every word overwritten each call, no atomics) ----
__device__ float g_rowsum[NN];
__device__ float g_diag[NN];
__device__ float g_cpart[SBLK * NN];  // per-block colsum partials (2 MB)
__device__ float g_Rf[NN * OUTC];     // per-i vector (incl. trace/totsum terms)
__device__ float g_Cc[NN * OUTC];     // per-j vector
__device__ float g_Dd[NN * OUTC];     // diagonal extras

// ---------------------------------------------------------------------------
// Single pass over A: rowsum + diag (direct) + colsum partials (per block).
// 256 blocks x 512 thr; block owns 8 rows; thread owns 4 fixed cols. MLP=8.
__global__ __launch_bounds__(512) void k_stats(const float* __restrict__ A) {
    __shared__ float sred[8][16];
    int t = threadIdx.x, lane = t & 31, w = t >> 5;   // 16 warps
    int r0 = blockIdx.x * 8;

    float4 ca = make_float4(0.f, 0.f, 0.f, 0.f);

    #pragma unroll
    for (int r = 0; r < 8; r++) {
        float4 v = ((const float4*)(A + (size_t)(r0 + r) * NN))[t];   // cols 4t..4t+3
        ca.x += v.x; ca.y += v.y; ca.z += v.z; ca.w += v.w;
        float rs = (v.x + v.y) + (v.z + v.w);
        #pragma unroll
        for (int off = 16; off; off >>= 1) rs += __shfl_xor_sync(0xffffffffu, rs, off);
        if (lane == 0) sred[r][w] = rs;
    }

    // colsum partials: coalesced float4 store, block-exclusive row of g_cpart
    *(float4*)(g_cpart + (size_t)blockIdx.x * NN + 4 * t) = ca;

    __syncthreads();
    if (t < 8) {
        float s = 0.f;
        #pragma unroll
        for (int q = 0; q < 16; q++) s += sred[t][q];
        g_rowsum[r0 + t] = s;
        g_diag[r0 + t]   = A[(size_t)(r0 + t) * NN + (r0 + t)];
    }
}

// ---------------------------------------------------------------------------
// k_pre: 32 blocks x 256. Block reduces colsum for its 64 columns from
// g_cpart (L2-resident), reduces trace/totsum, writes Rf/Cc/Dd float4 chunks.
__global__ __launch_bounds__(256) void k_pre(const float* __restrict__ W) {
    __shared__ float scp[4][64];
    __shared__ float scol[64];
    __shared__ float sr8[8], ss8[8];
    __shared__ float s_sc[2];
    int t = threadIdx.x, lane = t & 31, w = t >> 5;
    int j0 = blockIdx.x * 64;

    // ---- colsum for this block's 64 columns: 4 groups x 64 partials each ----
    {
        int cl = t & 63, cg = t >> 6;      // cg in 0..3
        int pbase = cg * 64;
        float acc = 0.f;
        #pragma unroll 8
        for (int p = pbase; p < pbase + 64; p++)
            acc += g_cpart[(size_t)p * NN + j0 + cl];
        scp[cg][cl] = acc;
        __syncthreads();
        if (t < 64) scol[t] = (scp[0][t] + scp[1][t]) + (scp[2][t] + scp[3][t]);
    }

    // ---- trace / totsum ----
    float tr = 0.f, ts = 0.f;
    #pragma unroll
    for (int q = 0; q < 8; q++) {
        tr += g_diag[t + 256 * q];
        ts += g_rowsum[t + 256 * q];
    }
    #pragma unroll
    for (int off = 16; off; off >>= 1) {
        tr += __shfl_xor_sync(0xffffffffu, tr, off);
        ts += __shfl_xor_sync(0xffffffffu, ts, off);
    }
    if (lane == 0) { sr8[w] = tr; ss8[w] = ts; }
    __syncthreads();
    if (t == 0) {
        float a = 0.f, b = 0.f;
        #pragma unroll
        for (int q = 0; q < 8; q++) { a += sr8[q]; b += ss8[q]; }
        s_sc[0] = a; s_sc[1] = b;
    }
    __syncthreads();
    float trv = s_sc[0], tsv = s_sc[1];

    // ---- per-i vectors: thread -> (i, float4 chunk) ----
    int il = t >> 2, c4 = t & 3;
    int i = j0 + il;
    float di = g_diag[i], ri = g_rowsum[i], ci = scol[il];

    float4 w0  = *(const float4*)(W + 0*16  + c4*4);
    float4 w1  = *(const float4*)(W + 1*16  + c4*4);
    float4 w2  = *(const float4*)(W + 2*16  + c4*4);
    float4 w3  = *(const float4*)(W + 3*16  + c4*4);
    float4 w4  = *(const float4*)(W + 4*16  + c4*4);
    float4 w5  = *(const float4*)(W + 5*16  + c4*4);
    float4 w6  = *(const float4*)(W + 6*16  + c4*4);
    float4 w7  = *(const float4*)(W + 7*16  + c4*4);
    float4 w8  = *(const float4*)(W + 8*16  + c4*4);
    float4 w9  = *(const float4*)(W + 9*16  + c4*4);
    float4 w10 = *(const float4*)(W + 10*16 + c4*4);
    float4 w13 = *(const float4*)(W + 13*16 + c4*4);
    float4 w14 = *(const float4*)(W + 14*16 + c4*4);

    float4 rf, cc, dd;
    rf.x = fmaf(di,w8.x, fmaf(ri,w9.x, fmaf(ci,w10.x, fmaf(trv,w13.x, tsv*w14.x))));
    rf.y = fmaf(di,w8.y, fmaf(ri,w9.y, fmaf(ci,w10.y, fmaf(trv,w13.y, tsv*w14.y))));
    rf.z = fmaf(di,w8.z, fmaf(ri,w9.z, fmaf(ci,w10.z, fmaf(trv,w13.z, tsv*w14.z))));
    rf.w = fmaf(di,w8.w, fmaf(ri,w9.w, fmaf(ci,w10.w, fmaf(trv,w13.w, tsv*w14.w))));
    cc.x = fmaf(di,w5.x, fmaf(ri,w6.x, ci*w7.x));
    cc.y = fmaf(di,w5.y, fmaf(ri,w6.y, ci*w7.y));
    cc.z = fmaf(di,w5.z, fmaf(ri,w6.z, ci*w7.z));
    cc.w = fmaf(di,w5.w, fmaf(ri,w6.w, ci*w7.w));
    dd.x = fmaf(di,w0.x, fmaf(ri,w1.x, fmaf(ci,w2.x, fmaf(trv,w3.x, tsv*w4.x))));
    dd.y = fmaf(di,w0.y, fmaf(ri,w1.y, fmaf(ci,w2.y, fmaf(trv,w3.y, tsv*w4.y))));
    dd.z = fmaf(di,w0.z, fmaf(ri,w1.z, fmaf(ci,w2.z, fmaf(trv,w3.z, tsv*w4.z))));
    dd.w = fmaf(di,w0.w, fmaf(ri,w1.w, fmaf(ci,w2.w, fmaf(trv,w3.w, tsv*w4.w))));

    *(float4*)(g_Rf + i*OUTC + c4*4) = rf;
    *(float4*)(g_Cc + i*OUTC + c4*4) = cc;
    *(float4*)(g_Dd + i*OUTC + c4*4) = dd;
}

// ---------------------------------------------------------------------------
__device__ __forceinline__ float4 f4add(float4 a, float4 b) {
    return make_float4(a.x + b.x, a.y + b.y, a.z + b.z, a.w + b.w);
}
__device__ __forceinline__ float4 f4fma(float s, float4 w, float4 acc) {
    return make_float4(fmaf(s, w.x, acc.x), fmaf(s, w.y, acc.y),
                       fmaf(s, w.z, acc.z), fmaf(s, w.w, acc.w));
}

// 32x32 output tile per block (R8 proven version). Lane layout:
// lane = jsub*4 + c4 so every STG.128 / Cc LDG.128 is a fully-contiguous
// 512B warp transaction.
__global__ __launch_bounds__(256, 4) void k_main(const float* __restrict__ A,
                                                 const float* __restrict__ W,
                                                 float* __restrict__ out) {
    __shared__ float sT[32][33];      // A[j][i] tile (transposed source)
    __shared__ float sA[32][33];      // A[i][j] tile
    __shared__ float4 sw11[4], sw12[4];
    int t = threadIdx.x;
    int j0 = blockIdx.x * 32, i0 = blockIdx.y * 32;

    if (t < 4)      sw11[t]     = *(const float4*)(W + 11*16 + t*4);
    else if (t < 8) sw12[t - 4] = *(const float4*)(W + 12*16 + (t-4)*4);

    #pragma unroll
    for (int k = 0; k < 4; k++) {
        int e = t + 256 * k;
        int r = e >> 5, c = e & 31;
        sT[r][c] = A[(size_t)(j0 + r) * NN + i0 + c];   // rows j0.., cols i0..
        sA[r][c] = A[(size_t)(i0 + r) * NN + j0 + c];   // rows i0.., cols j0..
    }
    __syncthreads();

    int wi = t >> 5, lane = t & 31;
    int jsub = lane >> 2, c4 = lane & 3;
    float4 w11c = sw11[c4], w12c = sw12[c4];

    // warp's i range: i0 + wi*4 .. +3 ; hoist Rf chunks (broadcast loads)
    float4 rf[4];
    #pragma unroll
    for (int k = 0; k < 4; k++)
        rf[k] = *(const float4*)(g_Rf + (size_t)(i0 + wi*4 + k) * OUTC + c4*4);

    #pragma unroll
    for (int jg = 0; jg < 4; jg++) {
        int jj = jg * 8 + jsub;
        int j  = j0 + jj;
        float4 cc = *(const float4*)(g_Cc + (size_t)j * OUTC + c4*4);  // coalesced

        #pragma unroll
        for (int k = 0; k < 4; k++) {
            int ii = wi * 4 + k;
            int i  = i0 + ii;
            float av = sA[ii][jj];
            float tv = sT[jj][ii];
            float4 o = f4fma(av, w12c, f4fma(tv, w11c, f4add(rf[k], cc)));
            if (i == j)
                o = f4add(o, *(const float4*)(g_Dd + (size_t)i * OUTC + c4*4));
            *(float4*)(out + ((size_t)i * NN + j) * OUTC + c4*4) = o;   // coalesced
        }
    }
}

extern "C" void kernel_launch(void* const* d_in, const int* in_sizes, int n_in,
                              void* d_out, int out_size) {
    const float* A = (const float*)d_in[0];
    const float* W = (const float*)d_in[1];
    float* out = (float*)d_out;

    k_stats<<<SBLK, 512>>>(A);
    k_pre<<<32, 256>>>(W);
    k_main<<<dim3(64, 64), 256>>>(A, W, out);
}